// round 1
// baseline (speedup 1.0000x reference)
#include <cuda_runtime.h>
#include <cstdint>

// Problem constants (ClassicMambaBlock: B=2, L=2048, Dm=1024, E=2048, N=16, R=64, K=3)
static constexpr int BSZ  = 2;
static constexpr int LEN  = 2048;
static constexpr int DM   = 1024;
static constexpr int EE   = 2048;
static constexpr int NN   = 16;
static constexpr int RR   = 64;
static constexpr int SEL  = RR + 2 * NN;   // 96
static constexpr int MTOT = BSZ * LEN;     // 4096

// ---------------- scratch (no cudaMalloc allowed) ----------------
__device__ float g_xz[MTOT * 2 * EE];     // [M, 4096] : cols [0,E)=xc, [E,2E)=z
__device__ float g_u[MTOT * EE];          // conv+silu output
__device__ float g_dbc[MTOT * SEL];       // [M, 96]: dt_low | B | C
__device__ float g_delta[MTOT * EE];      // softplus(dt)
__device__ float g_y[MTOT * EE];          // gated scan output

// ---------------- GEMM: C[M,N] = A[M,K] * B[N,K]^T (NT), packed f32x2 FMA ----------------
template<int BM, int BN, int BK, int TM, int TN, int EPI>
__global__ __launch_bounds__(256)
void sgemm_nt(const float* __restrict__ A, const float* __restrict__ Bw,
              float* __restrict__ C, int K,
              int lda, int ldb, int ldc, const float* __restrict__ bias)
{
    constexpr int NTX = BN / TN;
    constexpr int NTY = BM / TM;
    static_assert(NTX * NTY == 256, "block must be 256 threads");
    static_assert(TN % 2 == 0, "TN must be even for f32x2");

    __shared__ __align__(16) float As[BK][BM];
    __shared__ __align__(16) float Bs[BK][BN];

    const int tid = threadIdx.x;
    const int m0 = blockIdx.y * BM;
    const int n0 = blockIdx.x * BN;
    const int tx = tid % NTX;
    const int ty = tid / NTX;

    unsigned long long acc[TM][TN / 2];
#pragma unroll
    for (int i = 0; i < TM; i++)
#pragma unroll
        for (int j = 0; j < TN / 2; j++) acc[i][j] = 0ull;

    for (int kt = 0; kt < K; kt += BK) {
        // stage A tile (BM x BK), transposed into As[k][m]
        for (int i = tid; i < BM * BK / 4; i += 256) {
            int r = (i * 4) / BK, c = (i * 4) % BK;
            float4 v = *reinterpret_cast<const float4*>(A + (size_t)(m0 + r) * lda + kt + c);
            As[c + 0][r] = v.x; As[c + 1][r] = v.y; As[c + 2][r] = v.z; As[c + 3][r] = v.w;
        }
        // stage B tile (BN x BK), transposed into Bs[k][n]
        for (int i = tid; i < BN * BK / 4; i += 256) {
            int r = (i * 4) / BK, c = (i * 4) % BK;
            float4 v = *reinterpret_cast<const float4*>(Bw + (size_t)(n0 + r) * ldb + kt + c);
            Bs[c + 0][r] = v.x; Bs[c + 1][r] = v.y; Bs[c + 2][r] = v.z; Bs[c + 3][r] = v.w;
        }
        __syncthreads();

#pragma unroll
        for (int kk = 0; kk < BK; kk++) {
            unsigned long long b2[TN / 2];
#pragma unroll
            for (int j = 0; j < TN / 2; j++)
                b2[j] = *reinterpret_cast<const unsigned long long*>(&Bs[kk][tx * TN + 2 * j]);
#pragma unroll
            for (int i = 0; i < TM; i++) {
                float av = As[kk][ty * TM + i];
                unsigned long long a2;
                asm("mov.b64 %0, {%1, %1};" : "=l"(a2) : "r"(__float_as_uint(av)));
#pragma unroll
                for (int j = 0; j < TN / 2; j++)
                    asm("fma.rn.f32x2 %0, %1, %2, %0;" : "+l"(acc[i][j]) : "l"(a2), "l"(b2[j]));
            }
        }
        __syncthreads();
    }

#pragma unroll
    for (int i = 0; i < TM; i++) {
        const int row = m0 + ty * TM + i;
#pragma unroll
        for (int j = 0; j < TN / 2; j++) {
            unsigned int u0, u1;
            asm("mov.b64 {%0, %1}, %2;" : "=r"(u0), "=r"(u1) : "l"(acc[i][j]));
            float v0 = __uint_as_float(u0);
            float v1 = __uint_as_float(u1);
            const int col = n0 + tx * TN + 2 * j;
            if (EPI == 1) {  // softplus(x + bias)
                float x0 = v0 + bias[col];
                float x1 = v1 + bias[col + 1];
                v0 = (x0 > 20.f) ? x0 : log1pf(__expf(x0));
                v1 = (x1 > 20.f) ? x1 : log1pf(__expf(x1));
            }
            C[(size_t)row * ldc + col]     = v0;
            C[(size_t)row * ldc + col + 1] = v1;
        }
    }
}

// ---------------- causal depthwise conv1d (K=3) + bias + SiLU ----------------
__global__ __launch_bounds__(256)
void conv_silu_kernel(const float* __restrict__ xz,
                      const float* __restrict__ cw,
                      const float* __restrict__ cb,
                      float* __restrict__ u)
{
    int idx = blockIdx.x * blockDim.x + threadIdx.x;   // over B*L*E = 8.4M
    int e = idx % EE;
    int bt = idx / EE;          // b*L + t
    int t = bt % LEN;
    const float* xc = xz + (size_t)(bt - t) * (2 * EE);  // start of (b, 0) row

    float acc = cb[e];
    float w0 = cw[e * 3 + 0], w1 = cw[e * 3 + 1], w2 = cw[e * 3 + 2];
    if (t >= 2) acc = fmaf(w0, xc[(size_t)(t - 2) * (2 * EE) + e], acc);
    if (t >= 1) acc = fmaf(w1, xc[(size_t)(t - 1) * (2 * EE) + e], acc);
    acc = fmaf(w2, xc[(size_t)t * (2 * EE) + e], acc);
    u[idx] = acc / (1.f + __expf(-acc));   // silu
}

// ---------------- selective scan (16 lanes per channel, state-per-lane) ----------------
__global__ __launch_bounds__(256)
void scan_kernel(const float* __restrict__ delta,
                 const float* __restrict__ u,
                 const float* __restrict__ dbc,
                 const float* __restrict__ xz,
                 const float* __restrict__ A_log,
                 const float* __restrict__ D_param,
                 float* __restrict__ yout)
{
    const int gid = blockIdx.x * (blockDim.x >> 4) + (threadIdx.x >> 4); // channel (b*E+e)
    const int n   = threadIdx.x & 15;
    const int b   = gid / EE;
    const int e   = gid % EE;

    const float An = -__expf(A_log[e * NN + n]);
    const float Dp = D_param[e];

    const float* dptr = delta + (size_t)b * LEN * EE + e;
    const float* uptr = u     + (size_t)b * LEN * EE + e;
    const float* zptr = xz    + (size_t)b * LEN * (2 * EE) + EE + e;
    const float* bptr = dbc   + (size_t)b * LEN * SEL + RR + n;
    const float* cptr = bptr + NN;
    float*       yptr = yout  + (size_t)b * LEN * EE + e;

    float h = 0.f;
    // prefetch t = 0
    float d_c = dptr[0], u_c = uptr[0], z_c = zptr[0], B_c = bptr[0], C_c = cptr[0];

    for (int t = 0; t < LEN; t++) {
        float d_n = 0.f, u_n = 0.f, z_n = 0.f, B_n = 0.f, C_n = 0.f;
        if (t + 1 < LEN) {
            d_n = dptr[(size_t)(t + 1) * EE];
            u_n = uptr[(size_t)(t + 1) * EE];
            z_n = zptr[(size_t)(t + 1) * (2 * EE)];
            B_n = bptr[(size_t)(t + 1) * SEL];
            C_n = cptr[(size_t)(t + 1) * SEL];
        }
        float dA = __expf(d_c * An);
        h = fmaf(dA, h, d_c * u_c * B_c);
        float p = h * C_c;
        p += __shfl_xor_sync(0xffffffffu, p, 1);
        p += __shfl_xor_sync(0xffffffffu, p, 2);
        p += __shfl_xor_sync(0xffffffffu, p, 4);
        p += __shfl_xor_sync(0xffffffffu, p, 8);
        if (n == 0) {
            float sz = z_c / (1.f + __expf(-z_c));        // silu(z)
            yptr[(size_t)t * EE] = (p + u_c * Dp) * sz;   // (y + u*D) * silu(z)
        }
        d_c = d_n; u_c = u_n; z_c = z_n; B_c = B_n; C_c = C_n;
    }
}

// ---------------- launch ----------------
extern "C" void kernel_launch(void* const* d_in, const int* in_sizes, int n_in,
                              void* d_out, int out_size)
{
    const float* x       = (const float*)d_in[0];
    const float* W_in    = (const float*)d_in[1];
    const float* conv_w  = (const float*)d_in[2];
    const float* conv_b  = (const float*)d_in[3];
    const float* W_sel   = (const float*)d_in[4];
    const float* dt_w    = (const float*)d_in[5];
    const float* dt_b    = (const float*)d_in[6];
    const float* A_log   = (const float*)d_in[7];
    const float* D_param = (const float*)d_in[8];
    const float* W_out   = (const float*)d_in[9];
    float* out = (float*)d_out;

    float *xz, *u, *dbc, *delta, *y;
    cudaGetSymbolAddress((void**)&xz,    g_xz);
    cudaGetSymbolAddress((void**)&u,     g_u);
    cudaGetSymbolAddress((void**)&dbc,   g_dbc);
    cudaGetSymbolAddress((void**)&delta, g_delta);
    cudaGetSymbolAddress((void**)&y,     g_y);

    // 1) xz = x @ W_in^T   [4096, 4096] (K=1024)
    sgemm_nt<128, 128, 16, 8, 8, 0>
        <<<dim3((2 * EE) / 128, MTOT / 128), 256>>>(x, W_in, xz, DM, DM, DM, 2 * EE, nullptr);

    // 2) u = silu(causal_dwconv(xc) + b)
    conv_silu_kernel<<<(MTOT * EE) / 256, 256>>>(xz, conv_w, conv_b, u);

    // 3) dbc = u @ W_sel^T   [4096, 96] (K=2048)
    sgemm_nt<32, 96, 16, 2, 6, 0>
        <<<dim3(1, MTOT / 32), 256>>>(u, W_sel, dbc, EE, EE, EE, SEL, nullptr);

    // 4) delta = softplus(dt_low @ dt_w^T + dt_b)   [4096, 2048] (K=64, lda=96)
    sgemm_nt<128, 128, 16, 8, 8, 1>
        <<<dim3(EE / 128, MTOT / 128), 256>>>(dbc, dt_w, delta, RR, SEL, RR, EE, dt_b);

    // 5) selective scan + D-skip + z-gating -> y
    scan_kernel<<<(BSZ * EE) / 16, 256>>>(delta, u, dbc, xz, A_log, D_param, y);

    // 6) out = y @ W_out^T   [4096, 1024] (K=2048)
    sgemm_nt<128, 128, 16, 8, 8, 0>
        <<<dim3(DM / 128, MTOT / 128), 256>>>(y, W_out, out, EE, EE, EE, DM, nullptr);
}

// round 3
// speedup vs baseline: 1.8410x; 1.8410x over previous
#include <cuda_runtime.h>
#include <cstdint>

// Problem constants (ClassicMambaBlock: B=2, L=2048, Dm=1024, E=2048, N=16, R=64, K=3)
static constexpr int BSZ  = 2;
static constexpr int LEN  = 2048;
static constexpr int DM   = 1024;
static constexpr int EE   = 2048;
static constexpr int NN   = 16;
static constexpr int RR   = 64;
static constexpr int SEL  = RR + 2 * NN;   // 96
static constexpr int MTOT = BSZ * LEN;     // 4096

// ---------------- scratch (no cudaMalloc allowed) ----------------
__device__ float g_xz[MTOT * 2 * EE];     // [M, 4096] : cols [0,E)=xc, [E,2E)=z
__device__ float g_u[MTOT * EE];          // conv+silu output
__device__ float g_dbc[MTOT * SEL];       // [M, 96]: dt_low | B | C
__device__ float g_delta[MTOT * EE];      // softplus(dt)
__device__ float g_y[MTOT * EE];          // gated scan output

// ================= helpers =================
__device__ __forceinline__ uint32_t smem_u32(const void* p) {
    uint32_t a;
    asm("{ .reg .u64 t; cvta.to.shared.u64 t, %1; cvt.u32.u64 %0, t; }" : "=r"(a) : "l"(p));
    return a;
}
__device__ __forceinline__ void cp_async16(uint32_t dst, const void* src) {
    asm volatile("cp.async.ca.shared.global [%0], [%1], 16;" :: "r"(dst), "l"(src));
}
__device__ __forceinline__ uint32_t f2tf32(float f) {
    uint32_t u;
    asm("cvt.rna.tf32.f32 %0, %1;" : "=r"(u) : "f"(f));
    return u;
}
__device__ __forceinline__ void mma_tf32(float* d, const uint32_t* a, const uint32_t* b) {
    asm volatile(
        "mma.sync.aligned.m16n8k8.row.col.f32.tf32.tf32.f32 "
        "{%0,%1,%2,%3}, {%4,%5,%6,%7}, {%8,%9}, {%0,%1,%2,%3};"
        : "+f"(d[0]), "+f"(d[1]), "+f"(d[2]), "+f"(d[3])
        : "r"(a[0]), "r"(a[1]), "r"(a[2]), "r"(a[3]), "r"(b[0]), "r"(b[1]));
}

// ================= tf32 tensor GEMM: C[M,N] = A[M,K] @ B[N,K]^T =================
// BK = 32 fp32. smem layout per operand: float index (k4*ROWS + (row ^ k4))*4 + (k%4)
// -> cp.async 16B stores and all mma-fragment LDS are bank-conflict-free.
// Double-buffered cp.async pipeline. EPI==1: softplus(x + bias[col]).
template<int BM, int BN, int WM, int WN, int EPI>
__global__ __launch_bounds__(256)
void mma_gemm(const float* __restrict__ A, const float* __restrict__ Bw,
              float* __restrict__ C, int K, int lda, int ldb, int ldc,
              const float* __restrict__ bias)
{
    constexpr int WARPS_M = BM / WM;
    constexpr int MT = WM / 16;
    constexpr int NT = WN / 8;
    constexpr int BUF = (BM + BN) * 32;            // floats per stage
    static_assert((BM / WM) * (BN / WN) == 8, "8 warps");

    extern __shared__ float smem[];
    const uint32_t smem_b = smem_u32(smem);

    const int tid  = threadIdx.x;
    const int lane = tid & 31, wid = tid >> 5;
    const int wm = wid % WARPS_M, wn = wid / WARPS_M;
    const int qr = lane >> 2, kin = lane & 3;
    const int m0 = blockIdx.y * BM, n0 = blockIdx.x * BN;

    float acc[MT][NT][4];
#pragma unroll
    for (int i = 0; i < MT; i++)
#pragma unroll
        for (int j = 0; j < NT; j++)
#pragma unroll
            for (int q = 0; q < 4; q++) acc[i][j][q] = 0.f;

    auto load_chunk = [&](int kt, int buf) {
        const uint32_t ab = smem_b + buf * BUF * 4;
        const uint32_t bb = ab + BM * 128;
#pragma unroll
        for (int it = 0; it < BM * 8 / 256; it++) {
            int idx = tid + it * 256;
            int r = idx >> 3, c = idx & 7;
            cp_async16(ab + (uint32_t)(c * BM + (r ^ c)) * 16,
                       A + (size_t)(m0 + r) * lda + kt + c * 4);
        }
#pragma unroll
        for (int it = 0; it < BN * 8 / 256; it++) {
            int idx = tid + it * 256;
            int r = idx >> 3, c = idx & 7;
            cp_async16(bb + (uint32_t)(c * BN + (r ^ c)) * 16,
                       Bw + (size_t)(n0 + r) * ldb + kt + c * 4);
        }
        asm volatile("cp.async.commit_group;" ::: "memory");
    };

    const int nch = K / 32;
    load_chunk(0, 0);

    for (int i = 0; i < nch; i++) {
        if (i + 1 < nch) {
            load_chunk((i + 1) * 32, (i + 1) & 1);
            asm volatile("cp.async.wait_group 1;" ::: "memory");
        } else {
            asm volatile("cp.async.wait_group 0;" ::: "memory");
        }
        __syncthreads();

        const float* As = smem + (i & 1) * BUF;
        const float* Bs = As + BM * 32;
#pragma unroll
        for (int ks = 0; ks < 4; ks++) {
            const int k4a = ks * 2, k4b = k4a + 1;
            uint32_t af[MT][4], bf[NT][2];
#pragma unroll
            for (int t = 0; t < MT; t++) {
                const int mb = wm * WM + t * 16;
                af[t][0] = f2tf32(As[(k4a * BM + mb +     (qr ^ k4a)) * 4 + kin]);
                af[t][1] = f2tf32(As[(k4a * BM + mb + 8 + (qr ^ k4a)) * 4 + kin]);
                af[t][2] = f2tf32(As[(k4b * BM + mb +     (qr ^ k4b)) * 4 + kin]);
                af[t][3] = f2tf32(As[(k4b * BM + mb + 8 + (qr ^ k4b)) * 4 + kin]);
            }
#pragma unroll
            for (int j = 0; j < NT; j++) {
                const int nb = wn * WN + j * 8;
                bf[j][0] = f2tf32(Bs[(k4a * BN + nb + (qr ^ k4a)) * 4 + kin]);
                bf[j][1] = f2tf32(Bs[(k4b * BN + nb + (qr ^ k4b)) * 4 + kin]);
            }
#pragma unroll
            for (int t = 0; t < MT; t++)
#pragma unroll
                for (int j = 0; j < NT; j++)
                    mma_tf32(acc[t][j], af[t], bf[j]);
        }
        __syncthreads();
    }

    // ---------------- epilogue ----------------
#pragma unroll
    for (int t = 0; t < MT; t++) {
#pragma unroll
        for (int j = 0; j < NT; j++) {
            const int row = m0 + wm * WM + t * 16 + qr;
            const int col = n0 + wn * WN + j * 8 + kin * 2;
            float v0 = acc[t][j][0], v1 = acc[t][j][1];
            float v2 = acc[t][j][2], v3 = acc[t][j][3];
            if (EPI == 1) {
                const float b0 = bias[col], b1 = bias[col + 1];
                float x0 = v0 + b0, x1 = v1 + b1, x2 = v2 + b0, x3 = v3 + b1;
                v0 = (x0 > 20.f) ? x0 : log1pf(__expf(x0));
                v1 = (x1 > 20.f) ? x1 : log1pf(__expf(x1));
                v2 = (x2 > 20.f) ? x2 : log1pf(__expf(x2));
                v3 = (x3 > 20.f) ? x3 : log1pf(__expf(x3));
            }
            *reinterpret_cast<float2*>(C + (size_t)row * ldc + col)       = make_float2(v0, v1);
            *reinterpret_cast<float2*>(C + (size_t)(row + 8) * ldc + col) = make_float2(v2, v3);
        }
    }
}

// ---------------- causal depthwise conv1d (K=3) + bias + SiLU ----------------
__global__ __launch_bounds__(256)
void conv_silu_kernel(const float* __restrict__ xz,
                      const float* __restrict__ cw,
                      const float* __restrict__ cb,
                      float* __restrict__ u)
{
    int idx = blockIdx.x * blockDim.x + threadIdx.x;   // over B*L*E = 8.4M
    int e = idx % EE;
    int bt = idx / EE;          // b*L + t
    int t = bt % LEN;
    const float* xc = xz + (size_t)(bt - t) * (2 * EE);  // start of (b, 0) row

    float acc = cb[e];
    float w0 = cw[e * 3 + 0], w1 = cw[e * 3 + 1], w2 = cw[e * 3 + 2];
    if (t >= 2) acc = fmaf(w0, xc[(size_t)(t - 2) * (2 * EE) + e], acc);
    if (t >= 1) acc = fmaf(w1, xc[(size_t)(t - 1) * (2 * EE) + e], acc);
    acc = fmaf(w2, xc[(size_t)t * (2 * EE) + e], acc);
    u[idx] = acc / (1.f + __expf(-acc));   // silu
}

// ---------------- selective scan (16 lanes per channel, state-per-lane) ----------------
__global__ __launch_bounds__(256)
void scan_kernel(const float* __restrict__ delta,
                 const float* __restrict__ u,
                 const float* __restrict__ dbc,
                 const float* __restrict__ xz,
                 const float* __restrict__ A_log,
                 const float* __restrict__ D_param,
                 float* __restrict__ yout)
{
    const int gid = blockIdx.x * (blockDim.x >> 4) + (threadIdx.x >> 4); // channel (b*E+e)
    const int n   = threadIdx.x & 15;
    const int b   = gid / EE;
    const int e   = gid % EE;

    const float An = -__expf(A_log[e * NN + n]);
    const float Dp = D_param[e];

    const float* dptr = delta + (size_t)b * LEN * EE + e;
    const float* uptr = u     + (size_t)b * LEN * EE + e;
    const float* zptr = xz    + (size_t)b * LEN * (2 * EE) + EE + e;
    const float* bptr = dbc   + (size_t)b * LEN * SEL + RR + n;
    const float* cptr = bptr + NN;
    float*       yptr = yout  + (size_t)b * LEN * EE + e;

    float h = 0.f;
    float d_c = dptr[0], u_c = uptr[0], z_c = zptr[0], B_c = bptr[0], C_c = cptr[0];

    for (int t = 0; t < LEN; t++) {
        float d_n = 0.f, u_n = 0.f, z_n = 0.f, B_n = 0.f, C_n = 0.f;
        if (t + 1 < LEN) {
            d_n = dptr[(size_t)(t + 1) * EE];
            u_n = uptr[(size_t)(t + 1) * EE];
            z_n = zptr[(size_t)(t + 1) * (2 * EE)];
            B_n = bptr[(size_t)(t + 1) * SEL];
            C_n = cptr[(size_t)(t + 1) * SEL];
        }
        float dA = __expf(d_c * An);
        h = fmaf(dA, h, d_c * u_c * B_c);
        float p = h * C_c;
        p += __shfl_xor_sync(0xffffffffu, p, 1);
        p += __shfl_xor_sync(0xffffffffu, p, 2);
        p += __shfl_xor_sync(0xffffffffu, p, 4);
        p += __shfl_xor_sync(0xffffffffu, p, 8);
        if (n == 0) {
            float sz = z_c / (1.f + __expf(-z_c));        // silu(z)
            yptr[(size_t)t * EE] = (p + u_c * Dp) * sz;   // (y + u*D) * silu(z)
        }
        d_c = d_n; u_c = u_n; z_c = z_n; B_c = B_n; C_c = C_n;
    }
}

// ---------------- launch ----------------
extern "C" void kernel_launch(void* const* d_in, const int* in_sizes, int n_in,
                              void* d_out, int out_size)
{
    const float* x       = (const float*)d_in[0];
    const float* W_in    = (const float*)d_in[1];
    const float* conv_w  = (const float*)d_in[2];
    const float* conv_b  = (const float*)d_in[3];
    const float* W_sel   = (const float*)d_in[4];
    const float* dt_w    = (const float*)d_in[5];
    const float* dt_b    = (const float*)d_in[6];
    const float* A_log   = (const float*)d_in[7];
    const float* D_param = (const float*)d_in[8];
    const float* W_out   = (const float*)d_in[9];
    float* out = (float*)d_out;

    float *xz, *u, *dbc, *delta, *y;
    cudaGetSymbolAddress((void**)&xz,    g_xz);
    cudaGetSymbolAddress((void**)&u,     g_u);
    cudaGetSymbolAddress((void**)&dbc,   g_dbc);
    cudaGetSymbolAddress((void**)&delta, g_delta);
    cudaGetSymbolAddress((void**)&y,     g_y);

    constexpr int SM_BIG   = 2 * (128 + 128) * 32 * 4;  // 65536
    constexpr int SM_SMALL = 2 * (32 + 96) * 32 * 4;    // 32768
    cudaFuncSetAttribute((const void*)mma_gemm<128, 128, 64, 32, 0>,
                         cudaFuncAttributeMaxDynamicSharedMemorySize, SM_BIG);
    cudaFuncSetAttribute((const void*)mma_gemm<128, 128, 64, 32, 1>,
                         cudaFuncAttributeMaxDynamicSharedMemorySize, SM_BIG);
    cudaFuncSetAttribute((const void*)mma_gemm<32, 96, 16, 24, 0>,
                         cudaFuncAttributeMaxDynamicSharedMemorySize, SM_SMALL);

    // 1) xz = x @ W_in^T   [4096, 4096], K=1024
    mma_gemm<128, 128, 64, 32, 0><<<dim3((2 * EE) / 128, MTOT / 128), 256, SM_BIG>>>(
        x, W_in, xz, DM, DM, DM, 2 * EE, nullptr);

    // 2) u = silu(causal_dwconv(xc) + b)
    conv_silu_kernel<<<(MTOT * EE) / 256, 256>>>(xz, conv_w, conv_b, u);

    // 3) dbc = u @ W_sel^T   [4096, 96], K=2048
    mma_gemm<32, 96, 16, 24, 0><<<dim3(1, MTOT / 32), 256, SM_SMALL>>>(
        u, W_sel, dbc, EE, EE, EE, SEL, nullptr);

    // 4) delta = softplus(dt_low @ dt_w^T + dt_b)   [4096, 2048], K=64, lda=96
    mma_gemm<128, 128, 64, 32, 1><<<dim3(EE / 128, MTOT / 128), 256, SM_BIG>>>(
        dbc, dt_w, delta, RR, SEL, RR, EE, dt_b);

    // 5) selective scan + D-skip + z-gating -> y
    scan_kernel<<<(BSZ * EE) / 16, 256>>>(delta, u, dbc, xz, A_log, D_param, y);

    // 6) out = y @ W_out^T   [4096, 1024], K=2048
    mma_gemm<128, 128, 64, 32, 0><<<dim3(DM / 128, MTOT / 128), 256, SM_BIG>>>(
        y, W_out, out, EE, EE, EE, DM, nullptr);
}